// round 13
// baseline (speedup 1.0000x reference)
#include <cuda_runtime.h>
#include <cuda_bf16.h>
#include <cstdint>

// ===========================================================================
// Scratch (no allocations allowed): bf16 3-term concat operands.
// g_A: [2B=65536 rows, 3072]  = [Ahi | Ahi | Alo]   (384 MiB)
// g_B: [1024 rows,   3072]    = [Whi | Wlo | Whi]   (6 MiB)
// ===========================================================================
__device__ __align__(16) __nv_bfloat16 g_A[(size_t)65536 * 3072];
__device__ __align__(16) __nv_bfloat16 g_B[(size_t)1024 * 3072];

// ---------------------------------------------------------------------------
// PTX helpers — ONLY non-arch-suffixed instructions (target is plain sm_103):
// cp.async (sm_80), ldmatrix (sm_75), mma.sync bf16 (sm_80).
// ---------------------------------------------------------------------------
__device__ __forceinline__ uint32_t smem_u32(const void* p) {
    uint32_t a;
    asm("{ .reg .u64 t; cvta.to.shared.u64 t, %1; cvt.u32.u64 %0, t; }"
        : "=r"(a) : "l"(p));
    return a;
}
__device__ __forceinline__ void cp_async16(uint32_t s, const void* g) {
    asm volatile("cp.async.cg.shared.global [%0], [%1], 16;" :: "r"(s), "l"(g) : "memory");
}
#define CP_COMMIT() asm volatile("cp.async.commit_group;" ::: "memory")
#define CP_WAIT1()  asm volatile("cp.async.wait_group 1;" ::: "memory")

__device__ __forceinline__ void ldm4(uint32_t* r, uint32_t addr) {
    asm volatile("ldmatrix.sync.aligned.m8n8.x4.shared.b16 {%0,%1,%2,%3}, [%4];"
                 : "=r"(r[0]), "=r"(r[1]), "=r"(r[2]), "=r"(r[3]) : "r"(addr));
}
__device__ __forceinline__ void mma16816(float* c, const uint32_t* a,
                                         uint32_t b0, uint32_t b1) {
    asm volatile(
        "mma.sync.aligned.m16n8k16.row.col.f32.bf16.bf16.f32 "
        "{%0,%1,%2,%3}, {%4,%5,%6,%7}, {%8,%9}, {%0,%1,%2,%3};"
        : "+f"(c[0]), "+f"(c[1]), "+f"(c[2]), "+f"(c[3])
        : "r"(a[0]), "r"(a[1]), "r"(a[2]), "r"(a[3]), "r"(b0), "r"(b1));
}

#define BPB 4   // batches per block in the attention kernel
#define PW  68  // pitch for W / q / k smem rows (float4-aligned, conflict-free)

// ===========================================================================
// Kernel A: q/k projection + geodesic softmax + mixing, 4 batches per block.
// Fully float4-vectorized smem streams; 2 CTAs/SM (regs capped at 128).
// Writes x_mixed/v_mixed directly as bf16 hi/hi/lo planes into g_A.
// ===========================================================================
__global__ __launch_bounds__(256, 2) void attn_mix_kernel(
    const float* __restrict__ x, const float* __restrict__ v,
    const float* __restrict__ Wq, const float* __restrict__ bq,
    const float* __restrict__ Wk, const float* __restrict__ bk,
    int B)
{
    extern __shared__ float sm[];
    float* sWq = sm;                     // 64*68 = 4352
    float* sWk = sWq + 64 * PW;          // 4352
    float* sX  = sWk + 64 * PW;          // 4096
    float* sV  = sX  + BPB * 1024;       // 4096
    float* sQ  = sV  + BPB * 1024;       // 4352
    float* sK  = sQ  + 64 * PW;          // 4352
    float* sA  = sK  + 64 * PW;          // 1088
    float* sQs = sA  + 64 * 17;          // 64
    float* sKs = sQs + 64;               // 64

    const int t  = threadIdx.x;
    const int b0 = blockIdx.x * BPB;

    for (int i = t; i < 64 * 64; i += 256) {
        const int e = i >> 6, d = i & 63;
        sWq[e * PW + d] = Wq[i];
        sWk[e * PW + d] = Wk[i];
    }
    {
        const float4* x4 = (const float4*)(x + (size_t)b0 * 1024);
        const float4* v4 = (const float4*)(v + (size_t)b0 * 1024);
        float4* sX4 = (float4*)sX;
        float4* sV4 = (float4*)sV;
        #pragma unroll
        for (int i = t; i < BPB * 256; i += 256) { sX4[i] = x4[i]; sV4[i] = v4[i]; }
    }
    __syncthreads();

    // q = x @ Wq^T + bq ; k = x @ Wk^T + bk   (float4 LDS streams)
    for (int i = t; i < BPB * 1024; i += 256) {
        const int e  = i & 63;
        const int hh = i >> 6;
        const float4* xr = (const float4*)(sX  + hh * 64);
        const float4* wq = (const float4*)(sWq + e * PW);
        const float4* wk = (const float4*)(sWk + e * PW);
        float aq = bq[e], ak = bk[e];
        #pragma unroll
        for (int d = 0; d < 16; d++) {
            const float4 xv = xr[d];
            const float4 wqv = wq[d];
            const float4 wkv = wk[d];
            aq = fmaf(xv.x, wqv.x, aq); aq = fmaf(xv.y, wqv.y, aq);
            aq = fmaf(xv.z, wqv.z, aq); aq = fmaf(xv.w, wqv.w, aq);
            ak = fmaf(xv.x, wkv.x, ak); ak = fmaf(xv.y, wkv.y, ak);
            ak = fmaf(xv.z, wkv.z, ak); ak = fmaf(xv.w, wkv.w, ak);
        }
        sQ[hh * PW + e] = aq;
        sK[hh * PW + e] = ak;
    }
    __syncthreads();

    // squared norms per (batch, head) row
    if (t < 64) {
        const float4* qr = (const float4*)(sQ + t * PW);
        const float4* kr = (const float4*)(sK + t * PW);
        float sq = 0.f, sk = 0.f;
        #pragma unroll
        for (int e = 0; e < 16; e++) {
            const float4 q4 = qr[e], k4 = kr[e];
            sq = fmaf(q4.x, q4.x, sq); sq = fmaf(q4.y, q4.y, sq);
            sq = fmaf(q4.z, q4.z, sq); sq = fmaf(q4.w, q4.w, sq);
            sk = fmaf(k4.x, k4.x, sk); sk = fmaf(k4.y, k4.y, sk);
            sk = fmaf(k4.z, k4.z, sk); sk = fmaf(k4.w, k4.w, sk);
        }
        sQs[t] = sq;
        sKs[t] = sk;
    }
    __syncthreads();

    // -dist[h][g] = -(max(q2 + k2 - 2*q.k, 0))
    for (int i = t; i < BPB * 256; i += 256) {
        const int g  = i & 15;
        const int hh = i >> 4;
        const int bb = i >> 8;
        const float4* qr = (const float4*)(sQ + hh * PW);
        const float4* kr = (const float4*)(sK + (bb * 16 + g) * PW);
        float dot = 0.f;
        #pragma unroll
        for (int e = 0; e < 16; e++) {
            const float4 q4 = qr[e], k4 = kr[e];
            dot = fmaf(q4.x, k4.x, dot); dot = fmaf(q4.y, k4.y, dot);
            dot = fmaf(q4.z, k4.z, dot); dot = fmaf(q4.w, k4.w, dot);
        }
        float dist = sQs[hh] + sKs[bb * 16 + g] - 2.f * dot;
        dist = fmaxf(dist, 0.f);
        sA[hh * 17 + g] = -dist;
    }
    __syncthreads();

    // softmax over g (row of 16)
    if (t < 64) {
        float* r = sA + t * 17;
        float m = r[0];
        #pragma unroll
        for (int g = 1; g < 16; g++) m = fmaxf(m, r[g]);
        float s = 0.f;
        #pragma unroll
        for (int g = 0; g < 16; g++) { const float e = expf(r[g] - m); r[g] = e; s += e; }
        const float inv = 1.f / s;
        #pragma unroll
        for (int g = 0; g < 16; g++) r[g] *= inv;
    }
    __syncthreads();

    // mixed = attn @ {x, v}; float4 per thread; bf16 hi/lo planes out
    for (int i = t; i < BPB * 256; i += 256) {
        const int d4 = i & 15;            // which float4 of the 64-dim row
        const int hh = i >> 4;            // bb*16 + h
        const int bb = hh >> 4;
        const float* ar = sA + hh * 17;
        const float4* xb = (const float4*)(sX + bb * 16 * 64) + d4;
        const float4* vb = (const float4*)(sV + bb * 16 * 64) + d4;
        float4 ax = make_float4(0.f, 0.f, 0.f, 0.f);
        float4 av = make_float4(0.f, 0.f, 0.f, 0.f);
        #pragma unroll
        for (int g = 0; g < 16; g++) {
            const float a = ar[g];
            const float4 xv = xb[g * 16];
            const float4 vv = vb[g * 16];
            ax.x = fmaf(a, xv.x, ax.x); ax.y = fmaf(a, xv.y, ax.y);
            ax.z = fmaf(a, xv.z, ax.z); ax.w = fmaf(a, xv.w, ax.w);
            av.x = fmaf(a, vv.x, av.x); av.y = fmaf(a, vv.y, av.y);
            av.z = fmaf(a, vv.z, av.z); av.w = fmaf(a, vv.w, av.w);
        }
        const int col = (hh & 15) * 64 + d4 * 4;
        const size_t rowx = (size_t)(b0 + bb) * 3072;
        const size_t rowv = (size_t)(B + b0 + bb) * 3072;

        // hi/lo split, packed 8B stores
        __nv_bfloat162 hx0 = __floats2bfloat162_rn(ax.x, ax.y);
        __nv_bfloat162 hx1 = __floats2bfloat162_rn(ax.z, ax.w);
        __nv_bfloat162 lx0 = __floats2bfloat162_rn(ax.x - __bfloat162float(hx0.x),
                                                   ax.y - __bfloat162float(hx0.y));
        __nv_bfloat162 lx1 = __floats2bfloat162_rn(ax.z - __bfloat162float(hx1.x),
                                                   ax.w - __bfloat162float(hx1.y));
        __nv_bfloat162 hv0 = __floats2bfloat162_rn(av.x, av.y);
        __nv_bfloat162 hv1 = __floats2bfloat162_rn(av.z, av.w);
        __nv_bfloat162 lv0 = __floats2bfloat162_rn(av.x - __bfloat162float(hv0.x),
                                                   av.y - __bfloat162float(hv0.y));
        __nv_bfloat162 lv1 = __floats2bfloat162_rn(av.z - __bfloat162float(hv1.x),
                                                   av.w - __bfloat162float(hv1.y));
        uint2 hxu, lxu, hvu, lvu;
        hxu.x = *(uint32_t*)&hx0; hxu.y = *(uint32_t*)&hx1;
        lxu.x = *(uint32_t*)&lx0; lxu.y = *(uint32_t*)&lx1;
        hvu.x = *(uint32_t*)&hv0; hvu.y = *(uint32_t*)&hv1;
        lvu.x = *(uint32_t*)&lv0; lvu.y = *(uint32_t*)&lv1;

        *(uint2*)(&g_A[rowx + col])        = hxu;
        *(uint2*)(&g_A[rowx + 1024 + col]) = hxu;
        *(uint2*)(&g_A[rowx + 2048 + col]) = lxu;
        *(uint2*)(&g_A[rowv + col])        = hvu;
        *(uint2*)(&g_A[rowv + 1024 + col]) = hvu;
        *(uint2*)(&g_A[rowv + 2048 + col]) = lvu;
    }
}

// ===========================================================================
// Kernel W: convert Wo [1024,1024] fp32 -> g_B planes [Whi | Wlo | Whi]
// ===========================================================================
__global__ __launch_bounds__(256) void conv_wo_kernel(const float* __restrict__ Wo)
{
    const int i = blockIdx.x * 256 + threadIdx.x;   // 0 .. 1M-1
    const int e = i >> 10, k = i & 1023;
    const float w = Wo[i];
    const __nv_bfloat16 h = __float2bfloat16(w);
    const __nv_bfloat16 l = __float2bfloat16(w - __bfloat162float(h));
    const size_t r = (size_t)e * 3072;
    g_B[r + k] = h;
    g_B[r + 1024 + k] = l;
    g_B[r + 2048 + k] = h;
}

// ===========================================================================
// Kernel B: warp-level HMMA bf16 GEMM (mma.sync m16n8k16, fp32 accum).
// C[m][n] = bo[n] + sum_k g_A[m][k] * g_B[n][k].  M=65536, N=1024, K=3072.
// CTA tile 128x128, K-chunk 64, 3-stage cp.async pipeline, XOR-16B swizzle.
// ===========================================================================
#define KTOT    3072
#define G_KC    64
#define NCH     (KTOT / G_KC)       // 48
#define STAGE_B 32768               // A tile 16KB + B tile 16KB
#define GSMEM   (3 * STAGE_B)       // 98304

__device__ __forceinline__ void load_stage(
    const __nv_bfloat16* Ag, const __nv_bfloat16* Bg,
    uint32_t sbase, int c, int tid)
{
    const uint32_t sa = sbase + (uint32_t)(c % 3) * STAGE_B;
    const uint32_t sb = sa + 16384u;
    const int kb = c * G_KC;
    #pragma unroll
    for (int i = 0; i < 4; i++) {
        const int ch = tid + i * 256;
        const int row = ch >> 3, cc = ch & 7;
        cp_async16(sa + row * 128 + ((cc ^ (row & 7)) << 4),
                   Ag + (size_t)row * KTOT + kb + cc * 8);
    }
    #pragma unroll
    for (int i = 0; i < 4; i++) {
        const int ch = tid + i * 256;
        const int row = ch >> 3, cc = ch & 7;
        cp_async16(sb + row * 128 + ((cc ^ (row & 7)) << 4),
                   Bg + (size_t)row * KTOT + kb + cc * 8);
    }
    CP_COMMIT();
}

__global__ void __launch_bounds__(256) out_gemm_mma(
    const float* __restrict__ bo, float* __restrict__ C)
{
    extern __shared__ char smem[];
    const uint32_t sbase = smem_u32(smem);
    const int tid = threadIdx.x;
    const int lid = tid & 31;
    const int wid = tid >> 5;
    const int mw  = wid >> 1;          // 0..3  (m subtile of 32)
    const int nw  = wid & 1;           // 0..1  (n subtile of 64)
    const int m0  = blockIdx.y * 128;
    const int n0  = blockIdx.x * 128;

    const __nv_bfloat16* Ag = g_A + (size_t)m0 * KTOT;
    const __nv_bfloat16* Bg = g_B + (size_t)n0 * KTOT;

    float acc[2][8][4];
    #pragma unroll
    for (int i = 0; i < 2; i++)
        #pragma unroll
        for (int j = 0; j < 8; j++)
            #pragma unroll
            for (int q = 0; q < 4; q++) acc[i][j][q] = 0.f;

    load_stage(Ag, Bg, sbase, 0, tid);
    load_stage(Ag, Bg, sbase, 1, tid);

    const int lane15 = lid & 15;
    const int laneHi = lid >> 4;       // 0/1 -> +8 k elements (one 16B chunk)

    for (int c = 0; c < NCH; c++) {
        CP_WAIT1();                    // stage c resident (c+1 may be in flight)
        __syncthreads();
        if (c + 2 < NCH) load_stage(Ag, Bg, sbase, c + 2, tid);
        else             CP_COMMIT();  // empty group keeps the count uniform

        const uint32_t sa = sbase + (uint32_t)(c % 3) * STAGE_B;
        const uint32_t sb = sa + 16384u;

        #pragma unroll
        for (int kk = 0; kk < 4; kk++) {
            const int kc = kk * 2 + laneHi;    // 16B-chunk index within row
            uint32_t a[2][4];
            #pragma unroll
            for (int bm = 0; bm < 2; bm++) {
                const int row = mw * 32 + bm * 16 + lane15;
                ldm4(a[bm], sa + row * 128 + ((kc ^ (row & 7)) << 4));
            }
            #pragma unroll
            for (int bn = 0; bn < 4; bn++) {
                uint32_t b[4];
                const int row = nw * 64 + bn * 16 + lane15;
                ldm4(b, sb + row * 128 + ((kc ^ (row & 7)) << 4));
                #pragma unroll
                for (int bm = 0; bm < 2; bm++) {
                    mma16816(acc[bm][2 * bn],     a[bm], b[0], b[2]);
                    mma16816(acc[bm][2 * bn + 1], a[bm], b[1], b[3]);
                }
            }
        }
    }

    // epilogue: + bias, fp32 stores
    const int r4 = lid >> 2;
    const int c2 = (lid & 3) * 2;
    #pragma unroll
    for (int bm = 0; bm < 2; bm++) {
        const int row = m0 + mw * 32 + bm * 16 + r4;
        #pragma unroll
        for (int bn8 = 0; bn8 < 8; bn8++) {
            const int col = n0 + nw * 64 + bn8 * 8 + c2;
            const float bb0 = bo[col], bb1 = bo[col + 1];
            float* p0 = C + (size_t)row * 1024 + col;
            float* p1 = p0 + 8 * 1024;
            *(float2*)p0 = make_float2(acc[bm][bn8][0] + bb0, acc[bm][bn8][1] + bb1);
            *(float2*)p1 = make_float2(acc[bm][bn8][2] + bb0, acc[bm][bn8][3] + bb1);
        }
    }
}

// ===========================================================================
extern "C" void kernel_launch(void* const* d_in, const int* in_sizes, int n_in,
                              void* d_out, int out_size)
{
    const float* x  = (const float*)d_in[0];
    const float* v  = (const float*)d_in[1];
    const float* Wq = (const float*)d_in[2];
    const float* bq = (const float*)d_in[3];
    const float* Wk = (const float*)d_in[4];
    const float* bk = (const float*)d_in[5];
    const float* Wo = (const float*)d_in[6];
    const float* bo = (const float*)d_in[7];
    float* out = (float*)d_out;

    const int B = in_sizes[0] / 1024;   // 32768

    // attn smem: 4*64*68 + 2*4096 + 64*17 + 128 = 26816 floats (~105KB)
    const int attn_smem = (4 * 64 * PW + 2 * BPB * 1024 + 64 * 17 + 128) * (int)sizeof(float);
    cudaFuncSetAttribute(attn_mix_kernel,
                         cudaFuncAttributeMaxDynamicSharedMemorySize, attn_smem);
    cudaFuncSetAttribute(out_gemm_mma,
                         cudaFuncAttributeMaxDynamicSharedMemorySize, GSMEM);

    attn_mix_kernel<<<B / BPB, 256, attn_smem>>>(x, v, Wq, bq, Wk, bk, B);
    conv_wo_kernel<<<4096, 256>>>(Wo);

    dim3 grid(1024 / 128, (2 * B) / 128);   // (8, 512) — x fastest => A reuse in L2
    out_gemm_mma<<<grid, 256, GSMEM>>>(bo, out);
}

// round 14
// speedup vs baseline: 1.2632x; 1.2632x over previous
#include <cuda_runtime.h>
#include <cuda_bf16.h>
#include <cstdint>

// ===========================================================================
// Scratch: bf16 split operands.
// g_A: [2B=65536 rows, 2048] = [Ahi | Alo]   (256 MiB)
// g_B: [1024 rows,    2048] = [Whi | Wlo]   (4 MiB)
// GEMM does 3 passes over chunks: hi*hi, hi*lo, lo*hi  (lo*lo dropped, ~2^-18)
// ===========================================================================
__device__ __align__(16) __nv_bfloat16 g_A[(size_t)65536 * 2048];
__device__ __align__(16) __nv_bfloat16 g_B[(size_t)1024 * 2048];

// ---------------------------------------------------------------------------
// PTX helpers — ONLY non-arch-suffixed instructions (target is plain sm_103):
// cp.async (sm_80), ldmatrix (sm_75), mma.sync bf16 (sm_80).
// ---------------------------------------------------------------------------
__device__ __forceinline__ uint32_t smem_u32(const void* p) {
    uint32_t a;
    asm("{ .reg .u64 t; cvta.to.shared.u64 t, %1; cvt.u32.u64 %0, t; }"
        : "=r"(a) : "l"(p));
    return a;
}
__device__ __forceinline__ void cp_async16(uint32_t s, const void* g) {
    asm volatile("cp.async.cg.shared.global [%0], [%1], 16;" :: "r"(s), "l"(g) : "memory");
}
#define CP_COMMIT() asm volatile("cp.async.commit_group;" ::: "memory")
#define CP_WAIT1()  asm volatile("cp.async.wait_group 1;" ::: "memory")

__device__ __forceinline__ void ldm4(uint32_t* r, uint32_t addr) {
    asm volatile("ldmatrix.sync.aligned.m8n8.x4.shared.b16 {%0,%1,%2,%3}, [%4];"
                 : "=r"(r[0]), "=r"(r[1]), "=r"(r[2]), "=r"(r[3]) : "r"(addr));
}
__device__ __forceinline__ void mma16816(float* c, const uint32_t* a,
                                         uint32_t b0, uint32_t b1) {
    asm volatile(
        "mma.sync.aligned.m16n8k16.row.col.f32.bf16.bf16.f32 "
        "{%0,%1,%2,%3}, {%4,%5,%6,%7}, {%8,%9}, {%0,%1,%2,%3};"
        : "+f"(c[0]), "+f"(c[1]), "+f"(c[2]), "+f"(c[3])
        : "r"(a[0]), "r"(a[1]), "r"(a[2]), "r"(a[3]), "r"(b0), "r"(b1));
}

#define BPB 4   // batches per block in the attention kernel
#define PWT 68  // pitch (floats) for k-major W and for q/k rows: conflict-free
#define KA  2048

// ===========================================================================
// Kernel A: register-tiled projection + geodesic softmax + mixing.
// Crossbar-byte-minimized: every smem load is reused across a register tile.
// ===========================================================================
__global__ __launch_bounds__(256, 2) void attn_mix_kernel(
    const float* __restrict__ x, const float* __restrict__ v,
    const float* __restrict__ Wq, const float* __restrict__ bq,
    const float* __restrict__ Wk, const float* __restrict__ bk,
    int B)
{
    extern __shared__ float sm[];
    float* sWqT = sm;                    // [64 k][68] k-major
    float* sWkT = sWqT + 64 * PWT;       // 4352
    float* sX   = sWkT + 64 * PWT;       // [64 hh][64]
    float* sV   = sX + BPB * 1024;       // 4096
    float* sQ   = sV + BPB * 1024;       // [64 hh][68]
    float* sK   = sQ + 64 * PWT;         // 4352
    float* sA   = sK + 64 * PWT;         // [64][17]
    float* sQs  = sA + 64 * 17;          // 64
    float* sKs  = sQs + 64;              // 64

    const int t  = threadIdx.x;
    const int tx = t & 15;
    const int ty = t >> 4;
    const int b0 = blockIdx.x * BPB;

    // W transposed into k-major layout (one-time; minor store conflicts OK)
    for (int i = t; i < 64 * 64; i += 256) {
        const int e = i >> 6, d = i & 63;
        sWqT[d * PWT + e] = Wq[i];
        sWkT[d * PWT + e] = Wk[i];
    }
    {
        const float4* x4 = (const float4*)(x + (size_t)b0 * 1024);
        const float4* v4 = (const float4*)(v + (size_t)b0 * 1024);
        float4* sX4 = (float4*)sX;
        float4* sV4 = (float4*)sV;
        #pragma unroll
        for (int i = t; i < BPB * 256; i += 256) { sX4[i] = x4[i]; sV4[i] = v4[i]; }
    }
    __syncthreads();

    // ---- projection: thread tile = 4 hh x 4 e, for q and k -----------------
    {
        const int hh0 = ty * 4, e0 = tx * 4;
        const float4 bq4 = *(const float4*)(bq + e0);
        const float4 bk4 = *(const float4*)(bk + e0);
        float4 aq[4], ak[4];
        #pragma unroll
        for (int i = 0; i < 4; i++) { aq[i] = bq4; ak[i] = bk4; }

        #pragma unroll 4
        for (int k4 = 0; k4 < 16; k4++) {
            float4 xr[4];
            #pragma unroll
            for (int i = 0; i < 4; i++)
                xr[i] = *(const float4*)&sX[(hh0 + i) * 64 + k4 * 4];
            #pragma unroll
            for (int j = 0; j < 4; j++) {
                const int k = k4 * 4 + j;
                const float4 wq4 = *(const float4*)&sWqT[k * PWT + e0];
                const float4 wk4 = *(const float4*)&sWkT[k * PWT + e0];
                #pragma unroll
                for (int i = 0; i < 4; i++) {
                    const float xs = j == 0 ? xr[i].x : j == 1 ? xr[i].y
                                   : j == 2 ? xr[i].z : xr[i].w;
                    aq[i].x = fmaf(xs, wq4.x, aq[i].x);
                    aq[i].y = fmaf(xs, wq4.y, aq[i].y);
                    aq[i].z = fmaf(xs, wq4.z, aq[i].z);
                    aq[i].w = fmaf(xs, wq4.w, aq[i].w);
                    ak[i].x = fmaf(xs, wk4.x, ak[i].x);
                    ak[i].y = fmaf(xs, wk4.y, ak[i].y);
                    ak[i].z = fmaf(xs, wk4.z, ak[i].z);
                    ak[i].w = fmaf(xs, wk4.w, ak[i].w);
                }
            }
        }
        #pragma unroll
        for (int i = 0; i < 4; i++) {
            *(float4*)&sQ[(hh0 + i) * PWT + e0] = aq[i];
            *(float4*)&sK[(hh0 + i) * PWT + e0] = ak[i];
        }
    }
    __syncthreads();

    // ---- squared norms -----------------------------------------------------
    if (t < 64) {
        const float4* qr = (const float4*)(sQ + t * PWT);
        const float4* kr = (const float4*)(sK + t * PWT);
        float sq = 0.f, sk = 0.f;
        #pragma unroll
        for (int e = 0; e < 16; e++) {
            const float4 q4 = qr[e], k4 = kr[e];
            sq = fmaf(q4.x, q4.x, sq); sq = fmaf(q4.y, q4.y, sq);
            sq = fmaf(q4.z, q4.z, sq); sq = fmaf(q4.w, q4.w, sq);
            sk = fmaf(k4.x, k4.x, sk); sk = fmaf(k4.y, k4.y, sk);
            sk = fmaf(k4.z, k4.z, sk); sk = fmaf(k4.w, k4.w, sk);
        }
        sQs[t] = sq;
        sKs[t] = sk;
    }
    __syncthreads();

    // ---- dist: thread tile = 2 hh x 2 g (g, g+8 for distinct banks) --------
    {
        const int ha = ty * 4 + (tx >> 3) * 2;   // hh pair {ha, ha+1}
        const int gl = tx & 7;                   // g pair {gl, gl+8}
        const int bb = ha >> 4;
        const int kr0 = (bb * 16 + gl) * PWT;
        const int kr1 = (bb * 16 + gl + 8) * PWT;
        float d00 = 0.f, d01 = 0.f, d10 = 0.f, d11 = 0.f;
        #pragma unroll 4
        for (int k4 = 0; k4 < 16; k4++) {
            const float4 qa = *(const float4*)&sQ[ha * PWT + k4 * 4];
            const float4 qb = *(const float4*)&sQ[(ha + 1) * PWT + k4 * 4];
            const float4 ka = *(const float4*)&sK[kr0 + k4 * 4];
            const float4 kb = *(const float4*)&sK[kr1 + k4 * 4];
            d00 = fmaf(qa.x, ka.x, d00); d00 = fmaf(qa.y, ka.y, d00);
            d00 = fmaf(qa.z, ka.z, d00); d00 = fmaf(qa.w, ka.w, d00);
            d01 = fmaf(qa.x, kb.x, d01); d01 = fmaf(qa.y, kb.y, d01);
            d01 = fmaf(qa.z, kb.z, d01); d01 = fmaf(qa.w, kb.w, d01);
            d10 = fmaf(qb.x, ka.x, d10); d10 = fmaf(qb.y, ka.y, d10);
            d10 = fmaf(qb.z, ka.z, d10); d10 = fmaf(qb.w, ka.w, d10);
            d11 = fmaf(qb.x, kb.x, d11); d11 = fmaf(qb.y, kb.y, d11);
            d11 = fmaf(qb.z, kb.z, d11); d11 = fmaf(qb.w, kb.w, d11);
        }
        const float qsa = sQs[ha], qsb = sQs[ha + 1];
        const float ksa = sKs[bb * 16 + gl], ksb = sKs[bb * 16 + gl + 8];
        sA[ha * 17 + gl]           = -fmaxf(qsa + ksa - 2.f * d00, 0.f);
        sA[ha * 17 + gl + 8]       = -fmaxf(qsa + ksb - 2.f * d01, 0.f);
        sA[(ha + 1) * 17 + gl]     = -fmaxf(qsb + ksa - 2.f * d10, 0.f);
        sA[(ha + 1) * 17 + gl + 8] = -fmaxf(qsb + ksb - 2.f * d11, 0.f);
    }
    __syncthreads();

    // ---- softmax over g ----------------------------------------------------
    if (t < 64) {
        float* r = sA + t * 17;
        float m = r[0];
        #pragma unroll
        for (int g = 1; g < 16; g++) m = fmaxf(m, r[g]);
        float s = 0.f;
        #pragma unroll
        for (int g = 0; g < 16; g++) { const float e = expf(r[g] - m); r[g] = e; s += e; }
        const float inv = 1.f / s;
        #pragma unroll
        for (int g = 0; g < 16; g++) r[g] *= inv;
    }
    __syncthreads();

    // ---- mixing: thread tile = 4 hh x 1 d4; x/v rows reused across hh ------
    {
        const int d4  = tx;             // float4 column 0..15
        const int hh0 = ty * 4;
        const int bb  = ty >> 2;
        float4 ax[4], av[4];
        #pragma unroll
        for (int i = 0; i < 4; i++) {
            ax[i] = make_float4(0.f, 0.f, 0.f, 0.f);
            av[i] = make_float4(0.f, 0.f, 0.f, 0.f);
        }
        #pragma unroll
        for (int g = 0; g < 16; g++) {
            const float4 xv = *(const float4*)&sX[(bb * 16 + g) * 64 + d4 * 4];
            const float4 vv = *(const float4*)&sV[(bb * 16 + g) * 64 + d4 * 4];
            #pragma unroll
            for (int i = 0; i < 4; i++) {
                const float a = sA[(hh0 + i) * 17 + g];
                ax[i].x = fmaf(a, xv.x, ax[i].x); ax[i].y = fmaf(a, xv.y, ax[i].y);
                ax[i].z = fmaf(a, xv.z, ax[i].z); ax[i].w = fmaf(a, xv.w, ax[i].w);
                av[i].x = fmaf(a, vv.x, av[i].x); av[i].y = fmaf(a, vv.y, av[i].y);
                av[i].z = fmaf(a, vv.z, av[i].z); av[i].w = fmaf(a, vv.w, av[i].w);
            }
        }
        const size_t rowx = (size_t)(b0 + bb) * KA;
        const size_t rowv = (size_t)(B + b0 + bb) * KA;
        #pragma unroll
        for (int i = 0; i < 4; i++) {
            const int h   = (hh0 + i) & 15;
            const int col = h * 64 + d4 * 4;
            __nv_bfloat162 h0 = __floats2bfloat162_rn(ax[i].x, ax[i].y);
            __nv_bfloat162 h1 = __floats2bfloat162_rn(ax[i].z, ax[i].w);
            __nv_bfloat162 l0 = __floats2bfloat162_rn(ax[i].x - __bfloat162float(h0.x),
                                                      ax[i].y - __bfloat162float(h0.y));
            __nv_bfloat162 l1 = __floats2bfloat162_rn(ax[i].z - __bfloat162float(h1.x),
                                                      ax[i].w - __bfloat162float(h1.y));
            uint2 hu, lu;
            hu.x = *(uint32_t*)&h0; hu.y = *(uint32_t*)&h1;
            lu.x = *(uint32_t*)&l0; lu.y = *(uint32_t*)&l1;
            *(uint2*)(&g_A[rowx + col])        = hu;
            *(uint2*)(&g_A[rowx + 1024 + col]) = lu;

            h0 = __floats2bfloat162_rn(av[i].x, av[i].y);
            h1 = __floats2bfloat162_rn(av[i].z, av[i].w);
            l0 = __floats2bfloat162_rn(av[i].x - __bfloat162float(h0.x),
                                       av[i].y - __bfloat162float(h0.y));
            l1 = __floats2bfloat162_rn(av[i].z - __bfloat162float(h1.x),
                                       av[i].w - __bfloat162float(h1.y));
            hu.x = *(uint32_t*)&h0; hu.y = *(uint32_t*)&h1;
            lu.x = *(uint32_t*)&l0; lu.y = *(uint32_t*)&l1;
            *(uint2*)(&g_A[rowv + col])        = hu;
            *(uint2*)(&g_A[rowv + 1024 + col]) = lu;
        }
    }
}

// ===========================================================================
// Kernel W: convert Wo [1024,1024] fp32 -> g_B planes [Whi | Wlo]
// ===========================================================================
__global__ __launch_bounds__(256) void conv_wo_kernel(const float* __restrict__ Wo)
{
    const int i = blockIdx.x * 256 + threadIdx.x;   // 0 .. 1M-1
    const int e = i >> 10, k = i & 1023;
    const float w = Wo[i];
    const __nv_bfloat16 h = __float2bfloat16(w);
    const __nv_bfloat16 l = __float2bfloat16(w - __bfloat162float(h));
    const size_t r = (size_t)e * KA;
    g_B[r + k] = h;
    g_B[r + 1024 + k] = l;
}

// ===========================================================================
// Kernel B: warp-level HMMA bf16 GEMM (mma.sync m16n8k16, fp32 accum).
// Logical K = 3072 as 48 chunks; chunk c maps to A col ca*64, B col cb*64:
//   c<16: hi*hi   c in 16..31: hi*lo   c>=32: lo*hi
// ===========================================================================
#define NCH     48
#define STAGE_B 32768               // A tile 16KB + B tile 16KB
#define GSMEM   (3 * STAGE_B)       // 98304

__device__ __forceinline__ void load_stage(
    const __nv_bfloat16* Ag, const __nv_bfloat16* Bg,
    uint32_t sbase, int c, int tid)
{
    const uint32_t sa = sbase + (uint32_t)(c % 3) * STAGE_B;
    const uint32_t sb = sa + 16384u;
    const int ca = (c < 32) ? (c & 15) : ((c & 15) + 16);
    const int cb = (c < 32) ? c : (c - 32);
    const int kbA = ca * 64;
    const int kbB = cb * 64;
    #pragma unroll
    for (int i = 0; i < 4; i++) {
        const int ch = tid + i * 256;
        const int row = ch >> 3, cc = ch & 7;
        cp_async16(sa + row * 128 + ((cc ^ (row & 7)) << 4),
                   Ag + (size_t)row * KA + kbA + cc * 8);
    }
    #pragma unroll
    for (int i = 0; i < 4; i++) {
        const int ch = tid + i * 256;
        const int row = ch >> 3, cc = ch & 7;
        cp_async16(sb + row * 128 + ((cc ^ (row & 7)) << 4),
                   Bg + (size_t)row * KA + kbB + cc * 8);
    }
    CP_COMMIT();
}

__global__ void __launch_bounds__(256) out_gemm_mma(
    const float* __restrict__ bo, float* __restrict__ C)
{
    extern __shared__ char smem[];
    const uint32_t sbase = smem_u32(smem);
    const int tid = threadIdx.x;
    const int lid = tid & 31;
    const int wid = tid >> 5;
    const int mw  = wid >> 1;          // 0..3  (m subtile of 32)
    const int nw  = wid & 1;           // 0..1  (n subtile of 64)
    const int m0  = blockIdx.y * 128;
    const int n0  = blockIdx.x * 128;

    const __nv_bfloat16* Ag = g_A + (size_t)m0 * KA;
    const __nv_bfloat16* Bg = g_B + (size_t)n0 * KA;

    float acc[2][8][4];
    #pragma unroll
    for (int i = 0; i < 2; i++)
        #pragma unroll
        for (int j = 0; j < 8; j++)
            #pragma unroll
            for (int q = 0; q < 4; q++) acc[i][j][q] = 0.f;

    load_stage(Ag, Bg, sbase, 0, tid);
    load_stage(Ag, Bg, sbase, 1, tid);

    const int lane15 = lid & 15;
    const int laneHi = lid >> 4;       // 0/1 -> +8 k elements (one 16B chunk)

    for (int c = 0; c < NCH; c++) {
        CP_WAIT1();                    // stage c resident (c+1 may be in flight)
        __syncthreads();
        if (c + 2 < NCH) load_stage(Ag, Bg, sbase, c + 2, tid);
        else             CP_COMMIT();  // empty group keeps the count uniform

        const uint32_t sa = sbase + (uint32_t)(c % 3) * STAGE_B;
        const uint32_t sb = sa + 16384u;

        #pragma unroll
        for (int kk = 0; kk < 4; kk++) {
            const int kc = kk * 2 + laneHi;    // 16B-chunk index within row
            uint32_t a[2][4];
            #pragma unroll
            for (int bm = 0; bm < 2; bm++) {
                const int row = mw * 32 + bm * 16 + lane15;
                ldm4(a[bm], sa + row * 128 + ((kc ^ (row & 7)) << 4));
            }
            #pragma unroll
            for (int bn = 0; bn < 4; bn++) {
                uint32_t b[4];
                const int row = nw * 64 + bn * 16 + lane15;
                ldm4(b, sb + row * 128 + ((kc ^ (row & 7)) << 4));
                #pragma unroll
                for (int bm = 0; bm < 2; bm++) {
                    mma16816(acc[bm][2 * bn],     a[bm], b[0], b[2]);
                    mma16816(acc[bm][2 * bn + 1], a[bm], b[1], b[3]);
                }
            }
        }
    }

    // epilogue: + bias, fp32 stores
    const int r4 = lid >> 2;
    const int c2 = (lid & 3) * 2;
    #pragma unroll
    for (int bm = 0; bm < 2; bm++) {
        const int row = m0 + mw * 32 + bm * 16 + r4;
        #pragma unroll
        for (int bn8 = 0; bn8 < 8; bn8++) {
            const int col = n0 + nw * 64 + bn8 * 8 + c2;
            const float bb0 = bo[col], bb1 = bo[col + 1];
            float* p0 = C + (size_t)row * 1024 + col;
            float* p1 = p0 + 8 * 1024;
            *(float2*)p0 = make_float2(acc[bm][bn8][0] + bb0, acc[bm][bn8][1] + bb1);
            *(float2*)p1 = make_float2(acc[bm][bn8][2] + bb0, acc[bm][bn8][3] + bb1);
        }
    }
}

// ===========================================================================
extern "C" void kernel_launch(void* const* d_in, const int* in_sizes, int n_in,
                              void* d_out, int out_size)
{
    const float* x  = (const float*)d_in[0];
    const float* v  = (const float*)d_in[1];
    const float* Wq = (const float*)d_in[2];
    const float* bq = (const float*)d_in[3];
    const float* Wk = (const float*)d_in[4];
    const float* bk = (const float*)d_in[5];
    const float* Wo = (const float*)d_in[6];
    const float* bo = (const float*)d_in[7];
    float* out = (float*)d_out;

    const int B = in_sizes[0] / 1024;   // 32768

    // attn smem: 4*64*68 + 2*4096 + 64*17 + 128 = 26816 floats (~105KB)
    const int attn_smem = (4 * 64 * PWT + 2 * BPB * 1024 + 64 * 17 + 128) * (int)sizeof(float);
    cudaFuncSetAttribute(attn_mix_kernel,
                         cudaFuncAttributeMaxDynamicSharedMemorySize, attn_smem);
    cudaFuncSetAttribute(out_gemm_mma,
                         cudaFuncAttributeMaxDynamicSharedMemorySize, GSMEM);

    attn_mix_kernel<<<B / BPB, 256, attn_smem>>>(x, v, Wq, bq, Wk, bk, B);
    conv_wo_kernel<<<4096, 256>>>(Wo);

    dim3 grid(1024 / 128, (2 * B) / 128);   // (8, 512) — x fastest => A reuse in L2
    out_gemm_mma<<<grid, 256, GSMEM>>>(bo, out);
}